// round 1
// baseline (speedup 1.0000x reference)
#include <cuda_runtime.h>
#include <stdint.h>

#define NN 100000
#define NE 1000000
#define KD 128
#define OD 64

// Scratch: h = X @ W, 100000 x 64 fp32 = 25.6 MB (fits in L2 for the SpMM gather)
__device__ __align__(16) float g_h[(size_t)NN * OD];
__device__ int g_is64;

// Detect whether edge index arrays are int64 or int32.
// For int64 data with values in [0, 2^31), every odd 32-bit word is 0.
// 128 samples all-zero under int32 random node ids has ~0 probability.
__global__ void detect_kernel(const unsigned* __restrict__ er,
                              const unsigned* __restrict__ ec) {
    if (threadIdx.x == 0 && blockIdx.x == 0) {
        int all_zero = 1;
        #pragma unroll 1
        for (int i = 0; i < 64; i++) {
            all_zero &= (er[2 * i + 1] == 0u);
            all_zero &= (ec[2 * i + 1] == 0u);
        }
        g_is64 = all_zero;
    }
}

// h = X @ W. One thread per output row. W (32KB) in smem, broadcast LDS.128.
// Each lane streams its own X row contiguously (float4), full sector reuse.
__global__ __launch_bounds__(256) void gemm_kernel(const float* __restrict__ X,
                                                   const float* __restrict__ W) {
    __shared__ float4 Ws[KD * OD / 4];  // 128 x 16 float4 = 32KB
    const float4* W4 = reinterpret_cast<const float4*>(W);
    for (int i = threadIdx.x; i < KD * OD / 4; i += 256) Ws[i] = W4[i];
    __syncthreads();

    int row = blockIdx.x * 256 + threadIdx.x;
    if (row >= NN) return;

    const float4* xp = reinterpret_cast<const float4*>(X) + (size_t)row * (KD / 4);

    float4 acc[16];
    #pragma unroll
    for (int c = 0; c < 16; c++) acc[c] = make_float4(0.f, 0.f, 0.f, 0.f);

    #pragma unroll 2
    for (int k4 = 0; k4 < KD / 4; k4++) {
        float4 xv = __ldg(xp + k4);
        float xs0 = xv.x, xs1 = xv.y, xs2 = xv.z, xs3 = xv.w;
        const float4* wr0 = &Ws[(k4 * 4 + 0) * 16];
        const float4* wr1 = &Ws[(k4 * 4 + 1) * 16];
        const float4* wr2 = &Ws[(k4 * 4 + 2) * 16];
        const float4* wr3 = &Ws[(k4 * 4 + 3) * 16];
        #pragma unroll
        for (int c = 0; c < 16; c++) {
            float4 w;
            w = wr0[c];
            acc[c].x = fmaf(xs0, w.x, acc[c].x);
            acc[c].y = fmaf(xs0, w.y, acc[c].y);
            acc[c].z = fmaf(xs0, w.z, acc[c].z);
            acc[c].w = fmaf(xs0, w.w, acc[c].w);
            w = wr1[c];
            acc[c].x = fmaf(xs1, w.x, acc[c].x);
            acc[c].y = fmaf(xs1, w.y, acc[c].y);
            acc[c].z = fmaf(xs1, w.z, acc[c].z);
            acc[c].w = fmaf(xs1, w.w, acc[c].w);
            w = wr2[c];
            acc[c].x = fmaf(xs2, w.x, acc[c].x);
            acc[c].y = fmaf(xs2, w.y, acc[c].y);
            acc[c].z = fmaf(xs2, w.z, acc[c].z);
            acc[c].w = fmaf(xs2, w.w, acc[c].w);
            w = wr3[c];
            acc[c].x = fmaf(xs3, w.x, acc[c].x);
            acc[c].y = fmaf(xs3, w.y, acc[c].y);
            acc[c].z = fmaf(xs3, w.z, acc[c].z);
            acc[c].w = fmaf(xs3, w.w, acc[c].w);
        }
    }

    float4* hp = reinterpret_cast<float4*>(g_h) + (size_t)row * 16;
    #pragma unroll
    for (int c = 0; c < 16; c++) hp[c] = acc[c];
}

// SpMM scatter: 16 threads per edge, one float4 (16B) each.
// Vector reduction (red.global.add.v4.f32) quarters L2 atomic op count vs
// scalar atomicAdd: 16M no-return REDs instead of 64M.
__global__ __launch_bounds__(256) void spmm_kernel(const void* __restrict__ er_raw,
                                                   const void* __restrict__ ec_raw,
                                                   const float* __restrict__ ev,
                                                   float* __restrict__ out) {
    long long t = (long long)blockIdx.x * blockDim.x + threadIdx.x;
    long long e = t >> 4;
    int j = (int)(t & 15);
    if (e >= NE) return;

    long long r, c;
    if (g_is64) {
        r = ((const long long*)er_raw)[e];
        c = ((const long long*)ec_raw)[e];
    } else {
        r = (long long)((const int*)er_raw)[e];
        c = (long long)((const int*)ec_raw)[e];
    }
    float v = __ldg(ev + e);

    const float4* hp = reinterpret_cast<const float4*>(g_h) + c * 16 + j;
    float4 hv = __ldg(hp);

    float4* op = reinterpret_cast<float4*>(out) + r * 16 + j;
    asm volatile("red.global.add.v4.f32 [%0], {%1, %2, %3, %4};"
                 :: "l"(op), "f"(v * hv.x), "f"(v * hv.y),
                    "f"(v * hv.z), "f"(v * hv.w)
                 : "memory");
}

__global__ __launch_bounds__(256) void bias_relu_kernel(const float* __restrict__ bias,
                                                        float* __restrict__ out) {
    int i = blockIdx.x * blockDim.x + threadIdx.x;
    if (i >= NN * (OD / 4)) return;
    float4 b = reinterpret_cast<const float4*>(bias)[i & (OD / 4 - 1)];
    float4* op = reinterpret_cast<float4*>(out) + i;
    float4 o = *op;
    o.x = fmaxf(o.x + b.x, 0.f);
    o.y = fmaxf(o.y + b.y, 0.f);
    o.z = fmaxf(o.z + b.z, 0.f);
    o.w = fmaxf(o.w + b.w, 0.f);
    *op = o;
}

extern "C" void kernel_launch(void* const* d_in, const int* in_sizes, int n_in,
                              void* d_out, int out_size) {
    const float* X    = (const float*)d_in[0];
    const void*  er   = d_in[1];
    const void*  ec   = d_in[2];
    const float* ev   = (const float*)d_in[3];
    const float* W    = (const float*)d_in[4];
    const float* bias = (const float*)d_in[5];
    float* out = (float*)d_out;

    // out accumulates atomics; zero it first (graph-capturable memset node).
    cudaMemsetAsync(d_out, 0, (size_t)NN * OD * sizeof(float), 0);

    detect_kernel<<<1, 32>>>((const unsigned*)er, (const unsigned*)ec);

    gemm_kernel<<<(NN + 255) / 256, 256>>>(X, W);

    long long spmm_threads = (long long)NE * 16;
    spmm_kernel<<<(unsigned)((spmm_threads + 255) / 256), 256>>>(er, ec, ev, out);

    bias_relu_kernel<<<(NN * (OD / 4) + 255) / 256, 256>>>(bias, out);
}